// round 6
// baseline (speedup 1.0000x reference)
#include <cuda_runtime.h>
#include <cuda_bf16.h>
#include <cstdint>

// Problem constants
#define T_STEPS 512
#define BATCH   64
#define HID     512
#define GATES   1536   // 3*HID
#define NLAYERS 2

// Scratch (device globals; no allocation)
__device__ float g_gates[(size_t)T_STEPS * BATCH * GATES];    // L1 input gates
__device__ float g_gates2[(size_t)T_STEPS * BATCH * GATES];   // L2 input gates (fused)
__device__ float g_buf1[(size_t)T_STEPS * BATCH * HID];       // layer-1 output h1
__device__ float g_wfrag[(size_t)192 * 64 * 32 * 2];          // frag-ordered W_ih (L1)

// Per-batch-group software barriers (4 groups x 32 CTAs)
struct alignas(128) BarSt { unsigned arrive; unsigned gen; unsigned pad[30]; };
__device__ BarSt g_bars[4];

__device__ __forceinline__ uint32_t f32_to_tf32(float f) {
    uint32_t u;
    asm("cvt.rna.tf32.f32 %0, %1;" : "=r"(u) : "f"(f));
    return u;
}

#define MMA_TF32(acc, a0, a1, a2, a3, b0, b1)                                  \
    asm volatile(                                                              \
        "mma.sync.aligned.m16n8k8.row.col.f32.tf32.tf32.f32 "                  \
        "{%0,%1,%2,%3}, {%4,%5,%6,%7}, {%8,%9}, {%0,%1,%2,%3};\n"              \
        : "+f"((acc)[0]), "+f"((acc)[1]), "+f"((acc)[2]), "+f"((acc)[3])       \
        : "r"(a0), "r"(a1), "r"(a2), "r"(a3), "r"(b0), "r"(b1))

__device__ __forceinline__ void cp_async16(uint32_t dst, const void* src) {
    asm volatile("cp.async.cg.shared.global [%0], [%1], 16;" :: "r"(dst), "l"(src));
}

__device__ __forceinline__ unsigned ld_acq_gpu(unsigned* p) {
    unsigned v;
    asm volatile("ld.acquire.gpu.global.u32 %0, [%1];" : "=r"(v) : "l"(p) : "memory");
    return v;
}
__device__ __forceinline__ unsigned atom_add_rel_gpu(unsigned* p) {
    unsigned old;
    asm volatile("atom.add.release.gpu.global.u32 %0, [%1], 1;"
                 : "=r"(old) : "l"(p) : "memory");
    return old;
}

// ---------------------------------------------------------------------------
// Pre-convert W (N=1536, K=512 row-major fp32) into MMA B-fragment order.
// ---------------------------------------------------------------------------
__global__ __launch_bounds__(256) void conv_wfrag(
    const float* __restrict__ W, uint32_t* __restrict__ F)
{
    int idx = blockIdx.x * 256 + threadIdx.x;
    int r    = idx & 1;
    int lane = (idx >> 1) & 31;
    int k8   = (idx >> 6) & 63;
    int nt   = idx >> 12;
    int n = nt * 8 + (lane >> 2);
    int k = k8 * 8 + (lane & 3) + 4 * r;
    F[idx] = f32_to_tf32(W[(size_t)n * HID + k]);
}

// ---------------------------------------------------------------------------
// GEMM v2 (layer-1 input projection only)
// ---------------------------------------------------------------------------
#define AP 36

__global__ __launch_bounds__(256) void gemm_tf32_v2(
    const float* __restrict__ A, const uint32_t* __restrict__ Wf,
    const float* __restrict__ bias, float* __restrict__ C,
    int M, int N, int K)
{
    __shared__ float As[2][64][AP];

    const int bm  = blockIdx.y * 64;
    const int bnt = blockIdx.x * 16;
    const int tid = threadIdx.x;
    const int wid = tid >> 5;
    const int lane = tid & 31;
    const int wm = wid & 1;
    const int wn = wid >> 1;
    const int frow = lane >> 2;
    const int fk = lane & 3;

    float acc[2][4][4];
#pragma unroll
    for (int i = 0; i < 2; i++)
#pragma unroll
        for (int j = 0; j < 4; j++)
#pragma unroll
            for (int e = 0; e < 4; e++) acc[i][j][e] = 0.0f;

    const int lm = tid >> 3;
    const int lk = (tid & 7) * 4;

    auto issue_stage = [&](int k0, int buf) {
#pragma unroll
        for (int it = 0; it < 2; it++) {
            int m = lm + it * 32;
            uint32_t dst = (uint32_t)__cvta_generic_to_shared(&As[buf][m][lk]);
            cp_async16(dst, A + (size_t)(bm + m) * K + k0 + lk);
        }
        asm volatile("cp.async.commit_group;");
    };

    issue_stage(0, 0);
    int buf = 0;

    for (int k0 = 0; k0 < K; k0 += 32) {
        asm volatile("cp.async.wait_group 0;");
        __syncthreads();
        if (k0 + 32 < K) issue_stage(k0 + 32, buf ^ 1);

#pragma unroll
        for (int k8 = 0; k8 < 4; k8++) {
            const int kb = k8 * 8;
            const int k8g = (k0 >> 3) + k8;
            uint32_t b0[4], b1[4];
#pragma unroll
            for (int j = 0; j < 4; j++) {
                size_t nt = (size_t)(bnt + wn * 4 + j);
                const uint2 v = __ldg((const uint2*)(Wf + ((nt * 64 + k8g) * 32 + lane) * 2));
                b0[j] = v.x; b1[j] = v.y;
            }
            uint32_t a[2][4];
#pragma unroll
            for (int i = 0; i < 2; i++) {
                int r0 = wm * 32 + i * 16 + frow;
                a[i][0] = f32_to_tf32(As[buf][r0][kb + fk]);
                a[i][1] = f32_to_tf32(As[buf][r0 + 8][kb + fk]);
                a[i][2] = f32_to_tf32(As[buf][r0][kb + 4 + fk]);
                a[i][3] = f32_to_tf32(As[buf][r0 + 8][kb + 4 + fk]);
            }
#pragma unroll
            for (int i = 0; i < 2; i++)
#pragma unroll
                for (int j = 0; j < 4; j++)
                    MMA_TF32(acc[i][j], a[i][0], a[i][1], a[i][2], a[i][3],
                             b0[j], b1[j]);
        }
        buf ^= 1;
    }

#pragma unroll
    for (int i = 0; i < 2; i++) {
        int mrow = bm + wm * 32 + i * 16 + frow;
#pragma unroll
        for (int j = 0; j < 4; j++) {
            int ncol = (bnt + wn * 4 + j) * 8 + fk * 2;
            float c0 = bias[ncol], c1 = bias[ncol + 1];
            *(float2*)(C + (size_t)mrow * N + ncol) =
                make_float2(acc[i][j][0] + c0, acc[i][j][1] + c1);
            *(float2*)(C + (size_t)(mrow + 8) * N + ncol) =
                make_float2(acc[i][j][2] + c0, acc[i][j][3] + c1);
        }
    }
}

// ---------------------------------------------------------------------------
// Per-batch-group grid barrier (32 CTAs per group), acquire/release atomics.
// ---------------------------------------------------------------------------
__device__ __forceinline__ void group_barrier(int grp, unsigned nb)
{
    __syncthreads();
    if (threadIdx.x == 0) {
        unsigned gen0 = *(volatile unsigned*)&g_bars[grp].gen;
        unsigned prev = atom_add_rel_gpu(&g_bars[grp].arrive);
        if (prev == nb - 1) {
            *(volatile unsigned*)&g_bars[grp].arrive = 0;
            atom_add_rel_gpu(&g_bars[grp].gen);
        } else {
            while (ld_acq_gpu(&g_bars[grp].gen) == gen0) { }
        }
    }
    __syncthreads();
}

// ---------------------------------------------------------------------------
// Common tiling for recurrent kernels
// ---------------------------------------------------------------------------
#define HS_PITCH 520
#define PS_PITCH 100      // holds 96 partial cols (48 rec + 48 gx2) + pad
#define FUSED_SMEM_FLOATS (16 * HS_PITCH + 128 * PS_PITCH + 48 * 512)
#define FUSED_SMEM_BYTES (FUSED_SMEM_FLOATS * 4)
#define PLAIN_SMEM_FLOATS (16 * HS_PITCH + 128 * PS_PITCH)
#define PLAIN_SMEM_BYTES (PLAIN_SMEM_FLOATS * 4)

// ---------------------------------------------------------------------------
// Fused layer-1 kernel: recurrence + layer-2 input projection.
// While h1[t-1] is staged for the recurrent MMA, also compute
// gx2[t-1] = h1[t-1] @ W_ih2^T + b_ih2 using the same A fragments.
// ---------------------------------------------------------------------------
__global__ __launch_bounds__(256, 1) void gru_layer_mma_fused(
    const float* __restrict__ gx_all,  // (T, B, 3H) layer-1 input gates
    const float* __restrict__ h0,      // (B, H)
    const float* __restrict__ Whh,     // (3H, H)  layer-1 recurrent weights
    const float* __restrict__ bhh,     // (3H)
    const float* __restrict__ Wih2,    // (3H, H)  layer-2 input weights
    const float* __restrict__ bih2,    // (3H)
    float* __restrict__ out,           // (T, B, H) layer-1 h states
    float* __restrict__ gx2)           // (T, B, 3H) layer-2 input gates
{
    extern __shared__ float sm[];
    float* h_s = sm;                                   // [16][HS_PITCH]
    float* Ps  = sm + 16 * HS_PITCH;                   // [128][PS_PITCH]
    uint32_t* W2s = (uint32_t*)(sm + 16 * HS_PITCH + 128 * PS_PITCH); // [6][64][32][2]

    const int jt = blockIdx.x & 31;
    const int bt = blockIdx.x >> 5;
    const int j0 = jt * 16;
    const int b0 = bt * 16;
    const int tid = threadIdx.x;
    const int w = tid >> 5;
    const int lane = tid & 31;

    // ---- one-time: W_hh fragments -> registers; W_ih2 fragments -> SMEM
    uint32_t wb0[6][8], wb1[6][8];
    {
        const int colq = lane >> 2;
        const int kq = lane & 3;
#pragma unroll
        for (int tl = 0; tl < 6; tl++) {
            int g = tl >> 1;
            int col = j0 + (tl & 1) * 8 + colq;
            const float* wrow = Whh + (size_t)(g * HID + col) * HID;
#pragma unroll
            for (int kk = 0; kk < 8; kk++) {
                int k = (w * 8 + kk) * 8 + kq;
                wb0[tl][kk] = f32_to_tf32(wrow[k]);
                wb1[tl][kk] = f32_to_tf32(wrow[k + 4]);
            }
        }
    }
    for (int i = tid; i < 48 * 512; i += 256) {
        int row = i >> 9;            // 0..47
        int k = i & 511;
        int g = row >> 4;
        int jl = row & 15;
        int tl = g * 2 + (jl >> 3);
        int colq = jl & 7;
        int k8 = k >> 3, kk = k & 7;
        int ln = colq * 4 + (kk & 3);
        int rg = kk >> 2;
        W2s[((tl * 64 + k8) * 32 + ln) * 2 + rg] =
            f32_to_tf32(Wih2[(size_t)(g * HID + j0 + jl) * HID + k]);
    }

    const int gb = tid >> 4;
    const int gj = tid & 15;
    const int bg_g = b0 + gb;
    const int jg_g = j0 + gj;
    const float br_ = bhh[jg_g];
    const float bz_ = bhh[HID + jg_g];
    const float bn_ = bhh[2 * HID + jg_g];
    const float c2r = bih2[jg_g];
    const float c2z = bih2[HID + jg_g];
    const float c2n = bih2[2 * HID + jg_g];

    const int frow = lane >> 2;
    const int fk = lane & 3;
    const int pm = lane >> 2;
    const int pnc = 2 * (lane & 3);

    // prefetch t=0 input-side gates
    const float* gxp = gx_all + (size_t)bg_g * GATES;
    float xr = __ldg(gxp + jg_g);
    float xz = __ldg(gxp + HID + jg_g);
    float xn = __ldg(gxp + 2 * HID + jg_g);

    __syncthreads();   // W2s ready

    for (int t = 0; t < T_STEPS; t++) {
        const float* hprev = (t == 0) ? h0 : out + (size_t)(t - 1) * BATCH * HID;

        // stage h tile (16 x 512 fp32)
#pragma unroll
        for (int q = 0; q < 8; q++) {
            int f = q * 256 + tid;
            int rr = f >> 7;
            int c4 = f & 127;
            float4 v = *((const float4*)(hprev + (size_t)(b0 + rr) * HID) + c4);
            *(float4*)&h_s[rr * HS_PITCH + c4 * 4] = v;
        }
        __syncthreads();

        // ---- recurrent MMAs (B from registers)
        float acc[6][4];
#pragma unroll
        for (int tl = 0; tl < 6; tl++) {
            acc[tl][0] = 0.f; acc[tl][1] = 0.f; acc[tl][2] = 0.f; acc[tl][3] = 0.f;
        }
#pragma unroll
        for (int kk = 0; kk < 8; kk++) {
            int kbase = (w * 8 + kk) * 8;
            uint32_t a0 = f32_to_tf32(h_s[frow * HS_PITCH + kbase + fk]);
            uint32_t a1 = f32_to_tf32(h_s[(frow + 8) * HS_PITCH + kbase + fk]);
            uint32_t a2 = f32_to_tf32(h_s[frow * HS_PITCH + kbase + 4 + fk]);
            uint32_t a3 = f32_to_tf32(h_s[(frow + 8) * HS_PITCH + kbase + 4 + fk]);
#pragma unroll
            for (int tl = 0; tl < 6; tl++)
                MMA_TF32(acc[tl], a0, a1, a2, a3, wb0[tl][kk], wb1[tl][kk]);
        }
#pragma unroll
        for (int tl = 0; tl < 6; tl++) {
            *(float2*)&Ps[(w * 16 + pm) * PS_PITCH + tl * 8 + pnc] =
                make_float2(acc[tl][0], acc[tl][1]);
            *(float2*)&Ps[(w * 16 + pm + 8) * PS_PITCH + tl * 8 + pnc] =
                make_float2(acc[tl][2], acc[tl][3]);
        }

        // ---- fused gx2 MMAs (B from SMEM), staged tile = h1[t-1], valid t>=1
        if (t > 0) {
#pragma unroll
            for (int tl = 0; tl < 6; tl++) {
                acc[tl][0] = 0.f; acc[tl][1] = 0.f; acc[tl][2] = 0.f; acc[tl][3] = 0.f;
            }
#pragma unroll
            for (int kk = 0; kk < 8; kk++) {
                int k8g = w * 8 + kk;
                int kbase = k8g * 8;
                uint32_t a0 = f32_to_tf32(h_s[frow * HS_PITCH + kbase + fk]);
                uint32_t a1 = f32_to_tf32(h_s[(frow + 8) * HS_PITCH + kbase + fk]);
                uint32_t a2 = f32_to_tf32(h_s[frow * HS_PITCH + kbase + 4 + fk]);
                uint32_t a3 = f32_to_tf32(h_s[(frow + 8) * HS_PITCH + kbase + 4 + fk]);
#pragma unroll
                for (int tl = 0; tl < 6; tl++) {
                    uint2 bv = *(const uint2*)&W2s[((tl * 64 + k8g) * 32 + lane) * 2];
                    MMA_TF32(acc[tl], a0, a1, a2, a3, bv.x, bv.y);
                }
            }
#pragma unroll
            for (int tl = 0; tl < 6; tl++) {
                *(float2*)&Ps[(w * 16 + pm) * PS_PITCH + 48 + tl * 8 + pnc] =
                    make_float2(acc[tl][0], acc[tl][1]);
                *(float2*)&Ps[(w * 16 + pm + 8) * PS_PITCH + 48 + tl * 8 + pnc] =
                    make_float2(acc[tl][2], acc[tl][3]);
            }
        }
        __syncthreads();

        // ---- reduce + gating
        float hr = 0.f, hz = 0.f, hn = 0.f;
#pragma unroll
        for (int ww = 0; ww < 8; ww++) {
            const float* p = &Ps[(ww * 16 + gb) * PS_PITCH];
            hr += p[gj];
            hz += p[16 + gj];
            hn += p[32 + gj];
        }
        float r = 1.0f / (1.0f + __expf(-(xr + hr + br_)));
        float z = 1.0f / (1.0f + __expf(-(xz + hz + bz_)));
        float n = tanhf(xn + r * (hn + bn_));

        float hpv = h_s[gb * HS_PITCH + jg_g];
        out[(size_t)t * BATCH * HID + (size_t)bg_g * HID + jg_g] =
            (1.0f - z) * n + z * hpv;

        if (t > 0) {
            float s0 = 0.f, s1 = 0.f, s2 = 0.f;
#pragma unroll
            for (int ww = 0; ww < 8; ww++) {
                const float* p = &Ps[(ww * 16 + gb) * PS_PITCH + 48];
                s0 += p[gj];
                s1 += p[16 + gj];
                s2 += p[32 + gj];
            }
            float* gxo = gx2 + (size_t)(t - 1) * BATCH * GATES + (size_t)bg_g * GATES;
            gxo[jg_g] = s0 + c2r;
            gxo[HID + jg_g] = s1 + c2z;
            gxo[2 * HID + jg_g] = s2 + c2n;
        }

        // prefetch next step's input-side gates
        int tn = (t + 1 < T_STEPS) ? t + 1 : t;
        const float* gxn = gx_all + (size_t)tn * BATCH * GATES + (size_t)bg_g * GATES;
        xr = __ldg(gxn + jg_g);
        xz = __ldg(gxn + HID + jg_g);
        xn = __ldg(gxn + 2 * HID + jg_g);

        group_barrier(bt, 32);
    }

    // ---- epilogue: gx2[T-1] from h1[T-1] (needs cross-CTA slices -> after barrier)
    {
        const float* hlast = out + (size_t)(T_STEPS - 1) * BATCH * HID;
#pragma unroll
        for (int q = 0; q < 8; q++) {
            int f = q * 256 + tid;
            int rr = f >> 7;
            int c4 = f & 127;
            float4 v = *((const float4*)(hlast + (size_t)(b0 + rr) * HID) + c4);
            *(float4*)&h_s[rr * HS_PITCH + c4 * 4] = v;
        }
        __syncthreads();

        float acc[6][4];
#pragma unroll
        for (int tl = 0; tl < 6; tl++) {
            acc[tl][0] = 0.f; acc[tl][1] = 0.f; acc[tl][2] = 0.f; acc[tl][3] = 0.f;
        }
#pragma unroll
        for (int kk = 0; kk < 8; kk++) {
            int k8g = w * 8 + kk;
            int kbase = k8g * 8;
            uint32_t a0 = f32_to_tf32(h_s[frow * HS_PITCH + kbase + fk]);
            uint32_t a1 = f32_to_tf32(h_s[(frow + 8) * HS_PITCH + kbase + fk]);
            uint32_t a2 = f32_to_tf32(h_s[frow * HS_PITCH + kbase + 4 + fk]);
            uint32_t a3 = f32_to_tf32(h_s[(frow + 8) * HS_PITCH + kbase + 4 + fk]);
#pragma unroll
            for (int tl = 0; tl < 6; tl++) {
                uint2 bv = *(const uint2*)&W2s[((tl * 64 + k8g) * 32 + lane) * 2];
                MMA_TF32(acc[tl], a0, a1, a2, a3, bv.x, bv.y);
            }
        }
#pragma unroll
        for (int tl = 0; tl < 6; tl++) {
            *(float2*)&Ps[(w * 16 + pm) * PS_PITCH + 48 + tl * 8 + pnc] =
                make_float2(acc[tl][0], acc[tl][1]);
            *(float2*)&Ps[(w * 16 + pm + 8) * PS_PITCH + 48 + tl * 8 + pnc] =
                make_float2(acc[tl][2], acc[tl][3]);
        }
        __syncthreads();

        float s0 = 0.f, s1 = 0.f, s2 = 0.f;
#pragma unroll
        for (int ww = 0; ww < 8; ww++) {
            const float* p = &Ps[(ww * 16 + gb) * PS_PITCH + 48];
            s0 += p[gj];
            s1 += p[16 + gj];
            s2 += p[32 + gj];
        }
        float* gxo = gx2 + (size_t)(T_STEPS - 1) * BATCH * GATES + (size_t)bg_g * GATES;
        gxo[jg_g] = s0 + c2r;
        gxo[HID + jg_g] = s1 + c2z;
        gxo[2 * HID + jg_g] = s2 + c2n;
    }
}

// ---------------------------------------------------------------------------
// Plain recurrent kernel (layer 2)
// ---------------------------------------------------------------------------
__global__ __launch_bounds__(256, 1) void gru_layer_mma(
    const float* __restrict__ gx_all,
    const float* __restrict__ h0,
    const float* __restrict__ Whh,
    const float* __restrict__ bhh,
    float* __restrict__ out)
{
    extern __shared__ float sm[];
    float* h_s = sm;
    float* Ps  = sm + 16 * HS_PITCH;

    const int jt = blockIdx.x & 31;
    const int bt = blockIdx.x >> 5;
    const int j0 = jt * 16;
    const int b0 = bt * 16;
    const int tid = threadIdx.x;
    const int w = tid >> 5;
    const int lane = tid & 31;

    uint32_t wb0[6][8], wb1[6][8];
    {
        const int colq = lane >> 2;
        const int kq = lane & 3;
#pragma unroll
        for (int tl = 0; tl < 6; tl++) {
            int g = tl >> 1;
            int col = j0 + (tl & 1) * 8 + colq;
            const float* wrow = Whh + (size_t)(g * HID + col) * HID;
#pragma unroll
            for (int kk = 0; kk < 8; kk++) {
                int k = (w * 8 + kk) * 8 + kq;
                wb0[tl][kk] = f32_to_tf32(wrow[k]);
                wb1[tl][kk] = f32_to_tf32(wrow[k + 4]);
            }
        }
    }

    const int gb = tid >> 4;
    const int gj = tid & 15;
    const int bg_g = b0 + gb;
    const int jg_g = j0 + gj;
    const float br_ = bhh[jg_g];
    const float bz_ = bhh[HID + jg_g];
    const float bn_ = bhh[2 * HID + jg_g];

    const int frow = lane >> 2;
    const int fk = lane & 3;

    const float* gxp = gx_all + (size_t)bg_g * GATES;
    float xr = __ldg(gxp + jg_g);
    float xz = __ldg(gxp + HID + jg_g);
    float xn = __ldg(gxp + 2 * HID + jg_g);

    for (int t = 0; t < T_STEPS; t++) {
        const float* hprev = (t == 0) ? h0 : out + (size_t)(t - 1) * BATCH * HID;

#pragma unroll
        for (int q = 0; q < 8; q++) {
            int f = q * 256 + tid;
            int rr = f >> 7;
            int c4 = f & 127;
            float4 v = *((const float4*)(hprev + (size_t)(b0 + rr) * HID) + c4);
            *(float4*)&h_s[rr * HS_PITCH + c4 * 4] = v;
        }
        __syncthreads();

        float acc[6][4];
#pragma unroll
        for (int tl = 0; tl < 6; tl++) {
            acc[tl][0] = 0.f; acc[tl][1] = 0.f; acc[tl][2] = 0.f; acc[tl][3] = 0.f;
        }
#pragma unroll
        for (int kk = 0; kk < 8; kk++) {
            int kbase = (w * 8 + kk) * 8;
            uint32_t a0 = f32_to_tf32(h_s[frow * HS_PITCH + kbase + fk]);
            uint32_t a1 = f32_to_tf32(h_s[(frow + 8) * HS_PITCH + kbase + fk]);
            uint32_t a2 = f32_to_tf32(h_s[frow * HS_PITCH + kbase + 4 + fk]);
            uint32_t a3 = f32_to_tf32(h_s[(frow + 8) * HS_PITCH + kbase + 4 + fk]);
#pragma unroll
            for (int tl = 0; tl < 6; tl++)
                MMA_TF32(acc[tl], a0, a1, a2, a3, wb0[tl][kk], wb1[tl][kk]);
        }
        {
            int m = lane >> 2;
            int ncb = 2 * (lane & 3);
#pragma unroll
            for (int tl = 0; tl < 6; tl++) {
                *(float2*)&Ps[(w * 16 + m) * PS_PITCH + tl * 8 + ncb] =
                    make_float2(acc[tl][0], acc[tl][1]);
                *(float2*)&Ps[(w * 16 + m + 8) * PS_PITCH + tl * 8 + ncb] =
                    make_float2(acc[tl][2], acc[tl][3]);
            }
        }
        __syncthreads();

        float hr = 0.f, hz = 0.f, hn = 0.f;
#pragma unroll
        for (int ww = 0; ww < 8; ww++) {
            const float* p = &Ps[(ww * 16 + gb) * PS_PITCH];
            hr += p[gj];
            hz += p[16 + gj];
            hn += p[32 + gj];
        }
        float r = 1.0f / (1.0f + __expf(-(xr + hr + br_)));
        float z = 1.0f / (1.0f + __expf(-(xz + hz + bz_)));
        float n = tanhf(xn + r * (hn + bn_));

        float hpv = h_s[gb * HS_PITCH + jg_g];
        out[(size_t)t * BATCH * HID + (size_t)bg_g * HID + jg_g] =
            (1.0f - z) * n + z * hpv;

        int tn = (t + 1 < T_STEPS) ? t + 1 : t;
        const float* gxn = gx_all + (size_t)tn * BATCH * GATES + (size_t)bg_g * GATES;
        xr = __ldg(gxn + jg_g);
        xz = __ldg(gxn + HID + jg_g);
        xn = __ldg(gxn + 2 * HID + jg_g);

        if (t != T_STEPS - 1)
            group_barrier(bt, 32);
    }
}

// ---------------------------------------------------------------------------
extern "C" void kernel_launch(void* const* d_in, const int* in_sizes, int n_in,
                              void* d_out, int out_size)
{
    const float* x    = (const float*)d_in[0];
    const float* h0   = (const float*)d_in[1];
    const float* w_ih = (const float*)d_in[2];
    const float* w_hh = (const float*)d_in[3];
    const float* b_ih = (const float*)d_in[4];
    const float* b_hh = (const float*)d_in[5];
    float* out_final  = (float*)d_out;

    float* gates; float* gates2; float* buf1; uint32_t* wfrag;
    cudaGetSymbolAddress((void**)&gates, g_gates);
    cudaGetSymbolAddress((void**)&gates2, g_gates2);
    cudaGetSymbolAddress((void**)&buf1, g_buf1);
    cudaGetSymbolAddress((void**)&wfrag, g_wfrag);

    static int smem_configured = 0;
    if (!smem_configured) {
        cudaFuncSetAttribute(gru_layer_mma_fused,
                             cudaFuncAttributeMaxDynamicSharedMemorySize, FUSED_SMEM_BYTES);
        cudaFuncSetAttribute(gru_layer_mma,
                             cudaFuncAttributeMaxDynamicSharedMemorySize, PLAIN_SMEM_BYTES);
        smem_configured = 1;
    }

    const int M = T_STEPS * BATCH;
    const int K = HID;

    // ---- layer 1: input GEMM + fused (recurrence + layer-2 input projection)
    conv_wfrag<<<3072, 256>>>(w_ih, wfrag);
    dim3 ggrid(GATES / 128, M / 64);
    gemm_tf32_v2<<<ggrid, 256>>>(x, wfrag, b_ih, gates, M, GATES, K);

    gru_layer_mma_fused<<<128, 256, FUSED_SMEM_BYTES>>>(
        gates, h0, w_hh, b_hh,
        w_ih + (size_t)GATES * HID,   // layer-2 W_ih
        b_ih + GATES,                 // layer-2 b_ih
        buf1, gates2);

    // ---- layer 2: recurrence only (input gates already in gates2)
    gru_layer_mma<<<128, 256, PLAIN_SMEM_BYTES>>>(
        gates2, h0 + (size_t)BATCH * HID,
        w_hh + (size_t)GATES * HID, b_hh + GATES, out_final);
}